// round 13
// baseline (speedup 1.0000x reference)
#include <cuda_runtime.h>

#define XS 8192

extern __shared__ float4 DYN[];

__device__ __forceinline__ float4 shfl_xor_f4(float4 v, int d) {
    float4 r;
    r.x = __shfl_xor_sync(0xffffffffu, v.x, d);
    r.y = __shfl_xor_sync(0xffffffffu, v.y, d);
    r.z = __shfl_xor_sync(0xffffffffu, v.z, d);
    r.w = __shfl_xor_sync(0xffffffffu, v.w, d);
    return r;
}

__global__ void __launch_bounds__(512, 1) fused_kernel(
    const float* __restrict__ x,
    const float* __restrict__ w_diag,
    const float* __restrict__ w_off,
    const float* __restrict__ b1,
    const int*   __restrict__ perm,
    float*       __restrict__ out)
{
    // dynamic smem layout (float4 units):
    float4* Wp4   = DYN;            // 32 rows x 129 f4   [o][slot], slot=(i*16+mh)/4
    float4* Wm4   = DYN + 4128;
    float4* Sp4   = DYN + 8256;     // 4 rows x 129 f4    [s][slot]
    float4* Sm4   = DYN + 8772;
    float4* wdsh4 = DYN + 9288;     // 264: [iq*33 + o]
    float*  Tst   = (float*)(DYN + 9552);   // 256 floats: [pq][s][o]
    float*  bsh   = Tst + 256;              // 32

    const int b = blockIdx.x, t = threadIdx.x;
    const int k = b >> 3, sg = b & 7;       // block owns (k, samples 4sg..4sg+3)
    const float4* x4 = (const float4*)x;

    if (t < 32) bsh[t] = __ldg(&b1[t]);

    // finalize-role indices
    const int sL = t >> 7, aa = (t >> 3) & 15, og2 = t & 7;
    const int n2 = __ldg(&perm[k * 16 + aa]);

    // ---- w_diag column k -> smem [iq][o] ----
    {
        float* wdf = (float*)wdsh4;
#pragma unroll
        for (int j = 0; j < 2; j++) {
            int c = j * 512 + t, o = c >> 5, i = c & 31;
            wdf[((i >> 2) * 33 + o) * 4 + (i & 3)] = __ldg(&w_diag[c * 16 + k]);
        }
    }

    // ---- W±: cooperative load of w_off[:,k,:] (full column, 128 KB) --------
    {
        const float4* woff4 = (const float4*)w_off;   // [c][k][B/4]
        float2* WpF2 = (float2*)Wp4;   // row o: 258 f2
        float2* WmF2 = (float2*)Wm4;
        const int q = t & 7, cb = t >> 3;
#pragma unroll
        for (int jj = 0; jj < 16; jj++) {
            int c = jj * 64 + cb;                     // c = o*32+i
            float4 w = __ldg(&woff4[c * 128 + k * 8 + q]);
            int o = c >> 5, i = c & 31;
            WpF2[o * 258 + i * 8 + q] = make_float2(w.x + w.y, w.z + w.w);
            WmF2[o * 258 + i * 8 + q] = make_float2(w.x - w.y, w.z - w.w);
        }
    }

    // ---- S±: gather + pool 4 samples, all 32 B -----------------------------
    {
        const int s = t >> 7, B = (t >> 2) & 31, iq = t & 3;
        float4 a0 = make_float4(0.f, 0.f, 0.f, 0.f);
        float4 a1 = make_float4(0.f, 0.f, 0.f, 0.f);
#pragma unroll
        for (int r = 0; r < 8; r++) {
            int n = __ldg(&perm[8 * B + r]);
            int base = (4 * sg + s) * 2048 + n * 8;
            float4 v0 = __ldg(&x4[base + iq]);
            float4 v1 = __ldg(&x4[base + 4 + iq]);
            a0.x += v0.x; a0.y += v0.y; a0.z += v0.z; a0.w += v0.w;
            a1.x += v1.x; a1.y += v1.y; a1.z += v1.z; a1.w += v1.w;
        }
        float4 r0 = shfl_xor_f4(a0, 4);   // partner B^1 (t bit2 = B bit0)
        float4 r1 = shfl_xor_f4(a1, 4);
        const int mh = B >> 1;
        if ((B & 1) == 0) {               // Sp = S(2mh) + S(2mh+1)
            float* SpF = (float*)Sp4;
            SpF[s * 516 + (4 * iq + 0)  * 16 + mh] = a0.x + r0.x;
            SpF[s * 516 + (4 * iq + 1)  * 16 + mh] = a0.y + r0.y;
            SpF[s * 516 + (4 * iq + 2)  * 16 + mh] = a0.z + r0.z;
            SpF[s * 516 + (4 * iq + 3)  * 16 + mh] = a0.w + r0.w;
            SpF[s * 516 + (16 + 4 * iq + 0) * 16 + mh] = a1.x + r1.x;
            SpF[s * 516 + (16 + 4 * iq + 1) * 16 + mh] = a1.y + r1.y;
            SpF[s * 516 + (16 + 4 * iq + 2) * 16 + mh] = a1.z + r1.z;
            SpF[s * 516 + (16 + 4 * iq + 3) * 16 + mh] = a1.w + r1.w;
        } else {                          // Sm = S(2mh) - S(2mh+1) = recv - mine
            float* SmF = (float*)Sm4;
            SmF[s * 516 + (4 * iq + 0)  * 16 + mh] = r0.x - a0.x;
            SmF[s * 516 + (4 * iq + 1)  * 16 + mh] = r0.y - a0.y;
            SmF[s * 516 + (4 * iq + 2)  * 16 + mh] = r0.z - a0.z;
            SmF[s * 516 + (4 * iq + 3)  * 16 + mh] = r0.w - a0.w;
            SmF[s * 516 + (16 + 4 * iq + 0) * 16 + mh] = r1.x - a1.x;
            SmF[s * 516 + (16 + 4 * iq + 1) * 16 + mh] = r1.y - a1.y;
            SmF[s * 516 + (16 + 4 * iq + 2) * 16 + mh] = r1.z - a1.z;
            SmF[s * 516 + (16 + 4 * iq + 3) * 16 + mh] = r1.w - a1.w;
        }
    }
    __syncthreads();

    // ---- contraction: P/Q[s][o] = sum_slots W±[o]·S±[s], full K=512 --------
    {
        const int pq = t >> 8, og = (t >> 5) & 7, lane = t & 31;
        const float4* Wb = pq ? Wm4 : Wp4;
        const float4* Sb = pq ? Sm4 : Sp4;
        float accv[4][4];
#pragma unroll
        for (int j = 0; j < 16; j++) ((float*)accv)[j] = 0.f;
#pragma unroll
        for (int j = 0; j < 4; j++) {
            int slot = lane + 32 * j;
            float4 w4[4], s4[4];
#pragma unroll
            for (int oo = 0; oo < 4; oo++) w4[oo] = Wb[(og * 4 + oo) * 129 + slot];
#pragma unroll
            for (int ss = 0; ss < 4; ss++) s4[ss] = Sb[ss * 129 + slot];
#pragma unroll
            for (int ss = 0; ss < 4; ss++)
#pragma unroll
                for (int oo = 0; oo < 4; oo++)
                    accv[ss][oo] += w4[oo].x * s4[ss].x + w4[oo].y * s4[ss].y
                                  + w4[oo].z * s4[ss].z + w4[oo].w * s4[ss].w;
        }
        // 32-lane halving butterfly reduce (16 values -> 1 per lane)
        float* af = (float*)accv;
        float h8[8];
#pragma unroll
        for (int j = 0; j < 8; j++) {
            float A = af[j], B = af[j + 8];
            float ra = __shfl_xor_sync(0xffffffffu, A, 1);
            float rb = __shfl_xor_sync(0xffffffffu, B, 1);
            h8[j] = (lane & 1) ? (B + rb) : (A + ra);
        }
        float h4[4];
#pragma unroll
        for (int j = 0; j < 4; j++) {
            float A = h4[0], B;
            A = h8[j]; B = h8[j + 4];
            float ra = __shfl_xor_sync(0xffffffffu, A, 2);
            float rb = __shfl_xor_sync(0xffffffffu, B, 2);
            h4[j] = (lane & 2) ? (B + rb) : (A + ra);
        }
        float h2[2];
#pragma unroll
        for (int j = 0; j < 2; j++) {
            float A = h4[j], B = h4[j + 2];
            float ra = __shfl_xor_sync(0xffffffffu, A, 4);
            float rb = __shfl_xor_sync(0xffffffffu, B, 4);
            h2[j] = (lane & 4) ? (B + rb) : (A + ra);
        }
        float h1;
        {
            float A = h2[0], B = h2[1];
            float ra = __shfl_xor_sync(0xffffffffu, A, 8);
            float rb = __shfl_xor_sync(0xffffffffu, B, 8);
            h1 = (lane & 8) ? (B + rb) : (A + ra);
        }
        h1 += __shfl_xor_sync(0xffffffffu, h1, 16);
        if (lane < 16) {
            // value idx bits: b0->ss.hi, b1->ss.lo, b2->oo.hi, b3->oo.lo
            int sR  = ((lane & 1) << 1) | ((lane >> 1) & 1);
            int ooR = (((lane >> 2) & 1) << 1) | ((lane >> 3) & 1);
            Tst[pq * 128 + sR * 32 + og * 4 + ooR] = h1;
        }
    }

    // ---- diag GEMM (overlaps: wdsh already in smem since sync1) ------------
    float4 xr[8];
    {
        int base = (4 * sg + sL) * 2048 + n2 * 8;
#pragma unroll
        for (int iq = 0; iq < 8; iq++) xr[iq] = __ldg(&x4[base + iq]);
    }
    float acc2[4];
#pragma unroll
    for (int oo = 0; oo < 4; oo++) acc2[oo] = bsh[og2 + 8 * oo];
#pragma unroll
    for (int iq = 0; iq < 8; iq++) {
        float4 xv = xr[iq];
#pragma unroll
        for (int oo = 0; oo < 4; oo++) {
            float4 wv = wdsh4[iq * 33 + og2 + 8 * oo];
            acc2[oo] += wv.x * xv.x + wv.y * xv.y + wv.z * xv.z + wv.w * xv.w;
        }
    }
    __syncthreads();

    // ---- combine T = (P±Q)/512, add, store ----------------------------------
    const int pa = aa >> 3;
    float* orow = out + (4 * sg + sL) * XS + n2 * 32;
#pragma unroll
    for (int oo = 0; oo < 4; oo++) {
        int o = og2 + 8 * oo;
        float P = Tst[      sL * 32 + o];
        float Q = Tst[128 + sL * 32 + o];
        float tv = (pa ? (P - Q) : (P + Q)) * (1.0f / 512.0f);
        orow[o] = acc2[oo] + tv;
    }
}

// ---------------------------------------------------------------------------
extern "C" void kernel_launch(void* const* d_in, const int* in_sizes, int n_in,
                              void* d_out, int out_size)
{
    const float* x      = (const float*)d_in[0];
    const float* w_diag = (const float*)d_in[1];
    const float* w_off  = (const float*)d_in[2];
    const float* b1     = (const float*)d_in[3];
    const int*   perm   = (const int*)d_in[4];
    float* out = (float*)d_out;

    const int smem_bytes = 9552 * 16 + 288 * 4;   // 153,984 B
    cudaFuncSetAttribute(fused_kernel,
                         cudaFuncAttributeMaxDynamicSharedMemorySize, smem_bytes);
    fused_kernel<<<128, 512, smem_bytes>>>(x, w_diag, w_off, b1, perm, out);
}